// round 12
// baseline (speedup 1.0000x reference)
#include <cuda_runtime.h>
#include <math.h>

#define NN 4096
#define CH 256
#define NH 8
#define DD 32           // CH / NH
#define QROW 260        // padded smem V row (odd quad stride -> conflict-free)
#define JC 32           // j-chunk
#define NSPLIT 8        // j-range splits: grid 128*8=1024 ~ 6.92 waves @ occ1
#define CHUNKS_PER_SPLIT ((NN / JC) / NSPLIT)   // 16

// fused-kernel smem: Qf 16384 f + Kf 16384 f + V 32*260 f
#define SMEM_FLOATS (16384 + 16384 + 32 * QROW)
#define SMEM_BYTES (SMEM_FLOATS * 4)

typedef unsigned long long u64;
typedef unsigned int u32;

// ---- packed f32x2 helpers (Blackwell) ----
__device__ __forceinline__ u64 ffma2(u64 a, u64 b, u64 c) {
    u64 d;
    asm("fma.rn.f32x2 %0, %1, %2, %3;" : "=l"(d) : "l"(a), "l"(b), "l"(c));
    return d;
}
__device__ __forceinline__ u64 fmul2(u64 a, u64 b) {
    u64 d;
    asm("mul.rn.f32x2 %0, %1, %2;" : "=l"(d) : "l"(a), "l"(b));
    return d;
}
__device__ __forceinline__ float f2lo(u64 x) { return __uint_as_float((unsigned)x); }
__device__ __forceinline__ float f2hi(u64 x) { return __uint_as_float((unsigned)(x >> 32)); }
__device__ __forceinline__ u64 fpack(float l, float h) {
    return (u64)__float_as_uint(l) | ((u64)__float_as_uint(h) << 32);
}
__device__ __forceinline__ float to_tf32(float v) {
    u32 r;
    asm("cvt.rna.tf32.f32 %0, %1;" : "=r"(r) : "f"(v));
    return __uint_as_float(r);
}

// ---- mma.sync m16n8k8 tf32 ----
__device__ __forceinline__ void mma_tf32(float c[4], const u32 a[4], const u32 b[2]) {
    asm("mma.sync.aligned.m16n8k8.row.col.f32.tf32.tf32.f32 "
        "{%0,%1,%2,%3}, {%4,%5,%6,%7}, {%8,%9}, {%0,%1,%2,%3};"
        : "+f"(c[0]), "+f"(c[1]), "+f"(c[2]), "+f"(c[3])
        : "r"(a[0]), "r"(a[1]), "r"(a[2]), "r"(a[3]), "r"(b[0]), "r"(b[1]));
}

// device scratch (allocation-free rule: __device__ globals)
__device__ float g_V[NN * CH];
// Q fragments: [i-tile(256)][pl(2)][h(8)][ks(4)][lane(32)][r(4)]  (32 KB / i-tile)
__device__ float g_Qf[256 * 8192];
// K fragments: [j-chunk(128)][slice(4)][pl(2)][h(8)][ks(4)][lane(32)][r(2)] (64 KB / chunk)
__device__ float g_Kf[128 * 16384];
__device__ float g_AOp[NSPLIT][NN * DD];   // per-split partial attn_out

// ---------------------------------------------------------------------------
// Kernel 1: Q/K/V projections. V -> g_V; Q,K -> tf32 hi/lo MMA-fragment order.
// grid = (64, 4, 3)
// ---------------------------------------------------------------------------
__global__ __launch_bounds__(256) void qkv_kernel(
    const float* __restrict__ X,
    const float* __restrict__ Wq, const float* __restrict__ bq,
    const float* __restrict__ Wk, const float* __restrict__ bk,
    const float* __restrict__ Wv, const float* __restrict__ bv)
{
    __shared__ float As[16][64];   // As[k][m]
    __shared__ float Bs[16][64];   // Bs[k][n]

    const float* W;
    const float* b;
    if (blockIdx.z == 0)      { W = Wq; b = bq; }
    else if (blockIdx.z == 1) { W = Wk; b = bk; }
    else                      { W = Wv; b = bv; }

    const int m0 = blockIdx.x * 64;
    const int n0 = blockIdx.y * 64;
    const int tid = threadIdx.x;
    const int tx = tid & 15, ty = tid >> 4;

    float acc[4][4] = {};

    for (int k0 = 0; k0 < CH; k0 += 16) {
        {
            int k = tid & 15, mb = tid >> 4;
#pragma unroll
            for (int s = 0; s < 4; s++) {
                int m = mb + 16 * s;
                As[k][m] = X[(m0 + m) * CH + k0 + k];
            }
        }
        {
            int n = tid & 63, kb = tid >> 6;
#pragma unroll
            for (int s = 0; s < 4; s++) {
                int k = kb + 4 * s;
                Bs[k][n] = W[(k0 + k) * CH + n0 + n];
            }
        }
        __syncthreads();
#pragma unroll
        for (int k = 0; k < 16; k++) {
            float4 a4 = *(const float4*)&As[k][ty * 4];
            float4 b4 = *(const float4*)&Bs[k][tx * 4];
            float av[4] = {a4.x, a4.y, a4.z, a4.w};
            float bw[4] = {b4.x, b4.y, b4.z, b4.w};
#pragma unroll
            for (int i = 0; i < 4; i++)
#pragma unroll
                for (int j = 0; j < 4; j++)
                    acc[i][j] += av[i] * bw[j];
        }
        __syncthreads();
    }

#pragma unroll
    for (int i = 0; i < 4; i++) {
        int m = m0 + ty * 4 + i;
#pragma unroll
        for (int j = 0; j < 4; j++) {
            int n = n0 + tx * 4 + j;
            float v = acc[i][j] + b[n];
            if (blockIdx.z == 2) {
                g_V[m * CH + n] = v;
            } else {
                float hi = to_tf32(v);
                float lo = to_tf32(v - hi);
                int h = n & 7, dd = n >> 3;          // contraction index k = dd
                int ks = dd >> 3, kk = dd & 7;
                int tig = kk & 3, khalf = kk >> 2;
                if (blockIdx.z == 0) {
                    // A fragment (Q): row within i-tile
                    int it = m >> 4, mm = m & 15;
                    int gid = mm & 7, mhalf = mm >> 3;
                    int lane = gid * 4 + tig;
                    int r = mhalf + 2 * khalf;
                    size_t idx = (size_t)it * 8192 + (h * 4 + ks) * 128 + lane * 4 + r;
                    g_Qf[idx] = hi;
                    g_Qf[idx + 4096] = lo;          // pl=1 plane
                } else {
                    // B fragment (K): col within n8 slice
                    int jc = m >> 5, jj = m & 31;
                    int sl = jj >> 3, gid = jj & 7;
                    int lane = gid * 4 + tig;
                    int r = khalf;
                    size_t idx = (size_t)jc * 16384 + sl * 4096 +
                                 (h * 4 + ks) * 64 + lane * 2 + r;
                    g_Kf[idx] = hi;
                    g_Kf[idx + 2048] = lo;          // pl=1 plane
                }
            }
        }
    }
}

// ---------------------------------------------------------------------------
// Kernel 2: FUSED scores(MMA tf32x3) + head-softmax + attn write + SIMT AV.
// grid = (128 i-strips, NSPLIT), 256 threads = 8 warps (2 i-halves x 4 n8).
// ---------------------------------------------------------------------------
__global__ __launch_bounds__(256, 1) void attn_fused(
    const float* __restrict__ rel, float* __restrict__ attn_g)
{
    extern __shared__ float sm[];
    float* Qs  = sm;                 // 16384 floats (fragment-ready, 2 i-tiles)
    float* Ksm = sm + 16384;         // 16384 floats (fragment-ready, 1 chunk)
    float* Vs  = sm + 32768;         // [32][QROW]

    const int tid  = threadIdx.x;
    const int warp = tid >> 5;
    const int lane = tid & 31;
    const int gid  = lane >> 2;
    const int tig  = lane & 3;
    const int iw   = warp >> 2;      // i-half 0/1
    const int jw   = warp & 3;       // n8 slice 0..3
    const int ibase = blockIdx.x * 32;
    const int split = blockIdx.y;

    // Q fragment fill (once per block; coalesced)
    const float4* qsrc = (const float4*)(g_Qf + (size_t)blockIdx.x * 16384);
    for (int idx = tid; idx < 4096; idx += 256)
        ((float4*)Qs)[idx] = qsrc[idx];

    const int ig0  = ibase + iw * 16 + gid;
    const int ig1  = ig0 + 8;
    const int jcol = jw * 8 + 2 * tig;   // local col of c0; c1 = +1

    const float* aP = Qs + iw * 8192 + lane * 4;
    const float* bP = Ksm + jw * 4096 + lane * 2;

    float ao[2][DD];
#pragma unroll
    for (int rh = 0; rh < 2; rh++)
#pragma unroll
        for (int d = 0; d < DD; d++) ao[rh][d] = 0.f;

    for (int ci = 0; ci < CHUNKS_PER_SPLIT; ci++) {
        const int jc = split * CHUNKS_PER_SPLIT + ci;
        const int jbase = jc * JC;

        __syncthreads();   // prev chunk compute done (covers Q fill on ci==0)
        // K fragment + V fills (coalesced)
        {
            const float4* ksrc = (const float4*)(g_Kf + (size_t)jc * 16384);
            for (int idx = tid; idx < 4096; idx += 256)
                ((float4*)Ksm)[idx] = ksrc[idx];
            for (int idx = tid; idx < 2048; idx += 256) {
                int r = idx >> 6, c4 = idx & 63;
                *(float4*)&Vs[r * QROW + c4 * 4] =
                    *(const float4*)&g_V[(jbase + r) * CH + c4 * 4];
            }
        }

        // rel prefetch (latency hidden under MMA phase)
        const size_t rb0 = ((size_t)ig0 * NN + jbase + jcol) * NH;
        const size_t rb1 = ((size_t)ig1 * NN + jbase + jcol) * NH;
        float4 rp[8];
        rp[0] = *(const float4*)&rel[rb0];
        rp[1] = *(const float4*)&rel[rb0 + 4];
        rp[2] = *(const float4*)&rel[rb0 + 8];
        rp[3] = *(const float4*)&rel[rb0 + 12];
        rp[4] = *(const float4*)&rel[rb1];
        rp[5] = *(const float4*)&rel[rb1 + 4];
        rp[6] = *(const float4*)&rel[rb1 + 8];
        rp[7] = *(const float4*)&rel[rb1 + 12];

        __syncthreads();

        // ---- scores: tf32x3 MMA, all 8 heads ----
        float acc[NH][4];
#pragma unroll
        for (int h = 0; h < NH; h++)
#pragma unroll
            for (int p = 0; p < 4; p++) acc[h][p] = 0.f;

#pragma unroll
        for (int h = 0; h < NH; h++) {
#pragma unroll
            for (int ks = 0; ks < 4; ks++) {
                const float* ap = aP + (h * 4 + ks) * 128;
                const float* bp = bP + (h * 4 + ks) * 64;
                float4 ahf = *(const float4*)ap;
                float4 alf = *(const float4*)(ap + 4096);
                float2 bhf = *(const float2*)bp;
                float2 blf = *(const float2*)(bp + 2048);
                u32 ah[4] = {__float_as_uint(ahf.x), __float_as_uint(ahf.y),
                             __float_as_uint(ahf.z), __float_as_uint(ahf.w)};
                u32 al[4] = {__float_as_uint(alf.x), __float_as_uint(alf.y),
                             __float_as_uint(alf.z), __float_as_uint(alf.w)};
                u32 bh[2] = {__float_as_uint(bhf.x), __float_as_uint(bhf.y)};
                u32 bl[2] = {__float_as_uint(blf.x), __float_as_uint(blf.y)};
                mma_tf32(acc[h], ah, bh);
                mma_tf32(acc[h], ah, bl);
                mma_tf32(acc[h], al, bh);
            }
        }

        // ---- softmax over heads per fragment position, write attn ----
        // positions: p0=(ig0,jcol) p1=(ig0,jcol+1) p2=(ig1,jcol) p3=(ig1,jcol+1)
        u64 at2[4][4];   // packed attn per position (4 head-pairs)
#pragma unroll
        for (int p = 0; p < 4; p++) {
            float s[8];
            s[0] = acc[0][p] + ((const float*)&rp[2 * p])[0];
            s[1] = acc[1][p] + ((const float*)&rp[2 * p])[1];
            s[2] = acc[2][p] + ((const float*)&rp[2 * p])[2];
            s[3] = acc[3][p] + ((const float*)&rp[2 * p])[3];
            s[4] = acc[4][p] + ((const float*)&rp[2 * p + 1])[0];
            s[5] = acc[5][p] + ((const float*)&rp[2 * p + 1])[1];
            s[6] = acc[6][p] + ((const float*)&rp[2 * p + 1])[2];
            s[7] = acc[7][p] + ((const float*)&rp[2 * p + 1])[3];
            float m = s[0];
#pragma unroll
            for (int h = 1; h < 8; h++) m = fmaxf(m, s[h]);
            float sum = 0.f;
#pragma unroll
            for (int h = 0; h < 8; h++) { s[h] = __expf(s[h] - m); sum += s[h]; }
            const float inv = 1.f / sum;
#pragma unroll
            for (int h = 0; h < 8; h++) s[h] *= inv;
            const size_t rb = ((p & 1) ? 8 : 0) + ((p >> 1) ? rb1 : rb0);
            *(float4*)&attn_g[rb]     = make_float4(s[0], s[1], s[2], s[3]);
            *(float4*)&attn_g[rb + 4] = make_float4(s[4], s[5], s[6], s[7]);
#pragma unroll
            for (int q = 0; q < 4; q++)
                at2[p][q] = fpack(s[2 * q], s[2 * q + 1]);
        }

        // ---- AV: ao[rh][dd] += sum_h attn * V[j, dd*8+h] (f32x2 packed) ----
#pragma unroll
        for (int c = 0; c < 2; c++) {
            const float* vp = &Vs[(jcol + c) * QROW];
            const u64* a0 = at2[c];       // row ig0, col jcol+c
            const u64* a1 = at2[2 + c];   // row ig1, col jcol+c
#pragma unroll 4
            for (int dd = 0; dd < DD; dd++) {
                u64 v2[4];
                ulonglong2 t0 = *(const ulonglong2*)(vp + dd * 8);
                ulonglong2 t1 = *(const ulonglong2*)(vp + dd * 8 + 4);
                v2[0] = t0.x; v2[1] = t0.y; v2[2] = t1.x; v2[3] = t1.y;
                u64 s0 = fmul2(a0[0], v2[0]);
                s0 = ffma2(a0[1], v2[1], s0);
                s0 = ffma2(a0[2], v2[2], s0);
                s0 = ffma2(a0[3], v2[3], s0);
                u64 s1 = fmul2(a1[0], v2[0]);
                s1 = ffma2(a1[1], v2[1], s1);
                s1 = ffma2(a1[2], v2[2], s1);
                s1 = ffma2(a1[3], v2[3], s1);
                ao[0][dd] += f2lo(s0) + f2hi(s0);
                ao[1][dd] += f2lo(s1) + f2hi(s1);
            }
        }
    }

    // ---- reduce over tig (4 lanes), then over the 4 jw warps via smem ----
#pragma unroll
    for (int rh = 0; rh < 2; rh++)
#pragma unroll
        for (int dd = 0; dd < DD; dd++) {
            float v = ao[rh][dd];
            v += __shfl_xor_sync(0xffffffffu, v, 1);
            v += __shfl_xor_sync(0xffffffffu, v, 2);
            ao[rh][dd] = v;
        }

    __syncthreads();                    // all warps done with smem (Qs reuse)
    float* red = Qs;                    // [4 jw][32 row][32 dd] = 4096 floats
    if (tig == 0) {
#pragma unroll
        for (int rh = 0; rh < 2; rh++) {
            int row = iw * 16 + gid + rh * 8;
#pragma unroll
            for (int dd = 0; dd < DD; dd++)
                red[(jw * 32 + row) * 32 + dd] = ao[rh][dd];
        }
    }
    __syncthreads();

    float* aop = g_AOp[split];
    for (int idx = tid; idx < 1024; idx += 256) {
        int row = idx >> 5, dd = idx & 31;
        float s = red[(0 * 32 + row) * 32 + dd] + red[(1 * 32 + row) * 32 + dd] +
                  red[(2 * 32 + row) * 32 + dd] + red[(3 * 32 + row) * 32 + dd];
        aop[(ibase + row) * DD + dd] = s;
    }
}

// ---------------------------------------------------------------------------
// Kernel 3: sum split partials, then out = relu(ao @ W1 + b1) @ W2 + b2.
// ---------------------------------------------------------------------------
__global__ __launch_bounds__(256) void mlp_kernel(
    const float* __restrict__ W1, const float* __restrict__ b1,
    const float* __restrict__ W2, const float* __restrict__ b2,
    float* __restrict__ out)
{
    __shared__ float aos[16][DD];
    __shared__ float hs[16][CH];

    const int tid = threadIdx.x;
    const int r0 = blockIdx.x * 16;

    for (int idx = tid; idx < 16 * DD; idx += 256) {
        const int off = (r0 + idx / DD) * DD + (idx % DD);
        float a = 0.f;
#pragma unroll
        for (int s = 0; s < NSPLIT; s++) a += g_AOp[s][off];
        aos[idx / DD][idx % DD] = a;
    }
    __syncthreads();

    const int c = tid;
    float w[DD];
#pragma unroll
    for (int k = 0; k < DD; k++) w[k] = W1[k * CH + c];
    const float bb1 = b1[c];
#pragma unroll 4
    for (int r = 0; r < 16; r++) {
        float a = bb1;
#pragma unroll
        for (int k = 0; k < DD; k++) a += aos[r][k] * w[k];
        hs[r][c] = fmaxf(a, 0.f);
    }
    __syncthreads();

    float acc2[16];
    const float bb2 = b2[c];
#pragma unroll
    for (int r = 0; r < 16; r++) acc2[r] = bb2;
#pragma unroll 4
    for (int k = 0; k < CH; k++) {
        const float wv = W2[k * CH + c];
#pragma unroll
        for (int r = 0; r < 16; r++) acc2[r] += hs[r][k] * wv;
    }
#pragma unroll
    for (int r = 0; r < 16; r++) out[(r0 + r) * CH + c] = acc2[r];
}

// ---------------------------------------------------------------------------
extern "C" void kernel_launch(void* const* d_in, const int* in_sizes, int n_in,
                              void* d_out, int out_size)
{
    const float* X   = (const float*)d_in[0];
    const float* rel = (const float*)d_in[1];
    // d_in[2] = num_nodes (unused; N fixed at 4096)
    const float* Wq = (const float*)d_in[3];
    const float* bq = (const float*)d_in[4];
    const float* Wk = (const float*)d_in[5];
    const float* bk = (const float*)d_in[6];
    const float* Wv = (const float*)d_in[7];
    const float* bv = (const float*)d_in[8];
    const float* W1 = (const float*)d_in[9];
    const float* b1 = (const float*)d_in[10];
    const float* W2 = (const float*)d_in[11];
    const float* b2 = (const float*)d_in[12];

    float* out    = (float*)d_out;           // [4096, 256]
    float* attn_g = out + (size_t)NN * CH;   // [4096, 4096, 8]

    cudaFuncSetAttribute(attn_fused,
                         cudaFuncAttributeMaxDynamicSharedMemorySize, SMEM_BYTES);

    qkv_kernel<<<dim3(64, 4, 3), 256>>>(X, Wq, bq, Wk, bk, Wv, bv);
    attn_fused<<<dim3(NN / 32, NSPLIT), 256, SMEM_BYTES>>>(rel, attn_g);
    mlp_kernel<<<NN / 16, 256>>>(W1, b1, W2, b2, out);
}

// round 13
// speedup vs baseline: 1.1698x; 1.1698x over previous
#include <cuda_runtime.h>
#include <math.h>

#define NN 4096
#define CH 256
#define NH 8
#define DD 32            // CH / NH
#define KSPLIT 16        // j-range splits for AV kernel
#define AROW 68          // padded A smem row (mod 32 = 4 -> conflict-free frags)
#define BROW 40          // padded B smem row (mod 32 = 8 -> conflict-free frags)
// av kernel smem: 2*(64*AROW) + 2*(64*BROW) floats
#define AV_SMEM_FLOATS (2 * 64 * AROW + 2 * 64 * BROW)
#define AV_SMEM_BYTES (AV_SMEM_FLOATS * 4)

typedef unsigned long long u64;
typedef unsigned int u32;

__device__ __forceinline__ float to_tf32(float v) {
    u32 r;
    asm("cvt.rna.tf32.f32 %0, %1;" : "=r"(r) : "f"(v));
    return __uint_as_float(r);
}

// ---- mma.sync m16n8k8 tf32 ----
__device__ __forceinline__ void mma_tf32(float c[4], const u32 a[4], const u32 b[2]) {
    asm("mma.sync.aligned.m16n8k8.row.col.f32.tf32.tf32.f32 "
        "{%0,%1,%2,%3}, {%4,%5,%6,%7}, {%8,%9}, {%0,%1,%2,%3};"
        : "+f"(c[0]), "+f"(c[1]), "+f"(c[2]), "+f"(c[3])
        : "r"(a[0]), "r"(a[1]), "r"(a[2]), "r"(a[3]), "r"(b[0]), "r"(b[1]));
}

// device scratch (allocation-free rule: __device__ globals)
__device__ float g_Qhi[NH * NN * DD];   // per-head tf32 planes [h][i][dd]
__device__ float g_Qlo[NH * NN * DD];
__device__ float g_Khi[NH * NN * DD];
__device__ float g_Klo[NH * NN * DD];
__device__ float g_Vbh[NN * NH * DD];   // V in B-layout [j*8+h][dd], tf32 hi
__device__ float g_Vbl[NN * NH * DD];   // lo plane
__device__ float g_S[(size_t)NH * NN * NN];   // score planes [h][i][j]
__device__ float g_AOp[KSPLIT][NN * DD];      // per-split partial attn_out

// ---------------------------------------------------------------------------
// Kernel 1: Q/K/V projections.
// Q,K -> tf32 hi/lo per-head planes; V -> B-layout tf32 hi/lo planes.
// grid = (64, 4, 3)
// ---------------------------------------------------------------------------
__global__ __launch_bounds__(256) void qkv_kernel(
    const float* __restrict__ X,
    const float* __restrict__ Wq, const float* __restrict__ bq,
    const float* __restrict__ Wk, const float* __restrict__ bk,
    const float* __restrict__ Wv, const float* __restrict__ bv)
{
    __shared__ float As[16][64];   // As[k][m]
    __shared__ float Bs[16][64];   // Bs[k][n]

    const float* W;
    const float* b;
    if (blockIdx.z == 0)      { W = Wq; b = bq; }
    else if (blockIdx.z == 1) { W = Wk; b = bk; }
    else                      { W = Wv; b = bv; }

    const int m0 = blockIdx.x * 64;
    const int n0 = blockIdx.y * 64;
    const int tid = threadIdx.x;
    const int tx = tid & 15, ty = tid >> 4;

    float acc[4][4] = {};

    for (int k0 = 0; k0 < CH; k0 += 16) {
        {
            int k = tid & 15, mb = tid >> 4;
#pragma unroll
            for (int s = 0; s < 4; s++) {
                int m = mb + 16 * s;
                As[k][m] = X[(m0 + m) * CH + k0 + k];
            }
        }
        {
            int n = tid & 63, kb = tid >> 6;
#pragma unroll
            for (int s = 0; s < 4; s++) {
                int k = kb + 4 * s;
                Bs[k][n] = W[(k0 + k) * CH + n0 + n];
            }
        }
        __syncthreads();
#pragma unroll
        for (int k = 0; k < 16; k++) {
            float4 a4 = *(const float4*)&As[k][ty * 4];
            float4 b4 = *(const float4*)&Bs[k][tx * 4];
            float av[4] = {a4.x, a4.y, a4.z, a4.w};
            float bw[4] = {b4.x, b4.y, b4.z, b4.w};
#pragma unroll
            for (int i = 0; i < 4; i++)
#pragma unroll
                for (int j = 0; j < 4; j++)
                    acc[i][j] += av[i] * bw[j];
        }
        __syncthreads();
    }

#pragma unroll
    for (int i = 0; i < 4; i++) {
        int m = m0 + ty * 4 + i;
#pragma unroll
        for (int j = 0; j < 4; j++) {
            int n = n0 + tx * 4 + j;
            float v = acc[i][j] + b[n];
            float hi = to_tf32(v);
            float lo = to_tf32(v - hi);
            int h = n & 7, dd = n >> 3;
            if (blockIdx.z == 2) {
                size_t po = (size_t)(m * 8 + h) * DD + dd;
                g_Vbh[po] = hi;
                g_Vbl[po] = lo;
            } else {
                float* hiP = (blockIdx.z == 0) ? g_Qhi : g_Khi;
                float* loP = (blockIdx.z == 0) ? g_Qlo : g_Klo;
                size_t po = ((size_t)h * NN + m) * DD + dd;
                hiP[po] = hi;
                loP[po] = lo;
            }
        }
    }
}

// ---------------------------------------------------------------------------
// Kernel 2: batched per-head score GEMM, tf32x3: S_h = Q_h @ K_h^T.
// grid = (NN/64 j-tiles, NN/64 i-tiles, NH), 128 threads = 4 warps (2m x 2n).
// ---------------------------------------------------------------------------
__global__ __launch_bounds__(128) void score_gemm()
{
    __shared__ float Ah[64][36], Al[64][36];   // Q tile  [i][dd], pad 36
    __shared__ float Bh[64][36], Bl[64][36];   // K tile  [j][dd]

    const int h = blockIdx.z;
    const int i0 = blockIdx.y * 64;
    const int j0 = blockIdx.x * 64;
    const int tid = threadIdx.x;

    const float* qh = &g_Qhi[(size_t)h * NN * DD];
    const float* ql = &g_Qlo[(size_t)h * NN * DD];
    const float* kh = &g_Khi[(size_t)h * NN * DD];
    const float* kl = &g_Klo[(size_t)h * NN * DD];

    for (int idx = tid; idx < 512; idx += 128) {
        int r = idx >> 3, c4 = (idx & 7) * 4;
        *(float4*)&Ah[r][c4] = *(const float4*)&qh[(i0 + r) * DD + c4];
        *(float4*)&Al[r][c4] = *(const float4*)&ql[(i0 + r) * DD + c4];
        *(float4*)&Bh[r][c4] = *(const float4*)&kh[(j0 + r) * DD + c4];
        *(float4*)&Bl[r][c4] = *(const float4*)&kl[(j0 + r) * DD + c4];
    }
    __syncthreads();

    const int warp = tid >> 5;
    const int lane = tid & 31;
    const int gid = lane >> 2;      // 0..7
    const int tig = lane & 3;       // 0..3
    const int wm = (warp >> 1) * 32;
    const int wn = (warp & 1) * 32;

    float c[2][4][4];
#pragma unroll
    for (int mt = 0; mt < 2; mt++)
#pragma unroll
        for (int nt = 0; nt < 4; nt++)
#pragma unroll
            for (int p = 0; p < 4; p++) c[mt][nt][p] = 0.f;

#pragma unroll
    for (int ks = 0; ks < 4; ks++) {
        const int kb = ks * 8;
        u32 ah[2][4], al[2][4];
#pragma unroll
        for (int mt = 0; mt < 2; mt++) {
            int r0 = wm + mt * 16 + gid;
            ah[mt][0] = __float_as_uint(Ah[r0][kb + tig]);
            ah[mt][1] = __float_as_uint(Ah[r0 + 8][kb + tig]);
            ah[mt][2] = __float_as_uint(Ah[r0][kb + tig + 4]);
            ah[mt][3] = __float_as_uint(Ah[r0 + 8][kb + tig + 4]);
            al[mt][0] = __float_as_uint(Al[r0][kb + tig]);
            al[mt][1] = __float_as_uint(Al[r0 + 8][kb + tig]);
            al[mt][2] = __float_as_uint(Al[r0][kb + tig + 4]);
            al[mt][3] = __float_as_uint(Al[r0 + 8][kb + tig + 4]);
        }
#pragma unroll
        for (int nt = 0; nt < 4; nt++) {
            int jr = wn + nt * 8 + gid;
            u32 bh[2], bl[2];
            bh[0] = __float_as_uint(Bh[jr][kb + tig]);
            bh[1] = __float_as_uint(Bh[jr][kb + tig + 4]);
            bl[0] = __float_as_uint(Bl[jr][kb + tig]);
            bl[1] = __float_as_uint(Bl[jr][kb + tig + 4]);
#pragma unroll
            for (int mt = 0; mt < 2; mt++) {
                mma_tf32(c[mt][nt], ah[mt], bh);   // hi*hi
                mma_tf32(c[mt][nt], ah[mt], bl);   // hi*lo
                mma_tf32(c[mt][nt], al[mt], bh);   // lo*hi
            }
        }
    }

    float* Sp = &g_S[(size_t)h * NN * NN];
#pragma unroll
    for (int mt = 0; mt < 2; mt++) {
        int i = i0 + wm + mt * 16 + gid;
#pragma unroll
        for (int nt = 0; nt < 4; nt++) {
            int j = j0 + wn + nt * 8 + 2 * tig;
            size_t b0 = (size_t)i * NN + j;
            *(float2*)&Sp[b0] = make_float2(c[mt][nt][0], c[mt][nt][1]);
            *(float2*)&Sp[b0 + (size_t)8 * NN] = make_float2(c[mt][nt][2], c[mt][nt][3]);
        }
    }
}

// ---------------------------------------------------------------------------
// Kernel 3: FUSED head-softmax + attn write + AV GEMM (tf32x3 MMA).
// grid = (KSPLIT j-splits, 64 i-tiles), 128 threads = 4 warps, occ 4.
// Block: 64 i-rows x 256 j-cols; chunk = 8 j (K=64); acc = K-sweep partials.
// ---------------------------------------------------------------------------
__global__ __launch_bounds__(128, 4) void av_softmax(
    const float* __restrict__ rel, float* __restrict__ attn_g)
{
    extern __shared__ float sm[];
    float* Ah = sm;                         // [64][AROW]
    float* Al = sm + 64 * AROW;
    float* Bh = sm + 2 * 64 * AROW;         // [64][BROW]
    float* Bl = sm + 2 * 64 * AROW + 64 * BROW;

    const int tid  = threadIdx.x;
    const int warp = tid >> 5;
    const int lane = tid & 31;
    const int gid  = lane >> 2;
    const int tig  = lane & 3;
    const int i0   = blockIdx.y * 64;
    const int jr0  = blockIdx.x * (NN / KSPLIT);   // 256 j per block

    // staging identity: each thread owns 1 i-row, 4 consecutive j
    const int il = tid >> 1;            // 0..63
    const int jq = (tid & 1) * 4;       // 0 or 4
    const int ig = i0 + il;

    float acc[4][4];
#pragma unroll
    for (int nt = 0; nt < 4; nt++)
#pragma unroll
        for (int p = 0; p < 4; p++) acc[nt][p] = 0.f;

    for (int ci = 0; ci < 32; ci++) {
        const int jb = jr0 + ci * 8;
        __syncthreads();   // prev chunk's MMA done

        // ---- B staging: copy V hi/lo rows [jb*8 .. jb*8+63] ----
        for (int idx4 = tid; idx4 < 512; idx4 += 128) {
            int k = idx4 >> 3, c4 = (idx4 & 7) * 4;
            *(float4*)&Bh[k * BROW + c4] =
                *(const float4*)&g_Vbh[(size_t)(jb * 8 + k) * DD + c4];
            *(float4*)&Bl[k * BROW + c4] =
                *(const float4*)&g_Vbl[(size_t)(jb * 8 + k) * DD + c4];
        }

        // ---- A staging: S + rel -> softmax -> attn store + tf32 split ----
        {
            const int jg = jb + jq;
            float4 sS[8];
#pragma unroll
            for (int h = 0; h < 8; h++)
                sS[h] = *(const float4*)&g_S[(size_t)h * NN * NN +
                                             (size_t)ig * NN + jg];
            const size_t rb = ((size_t)ig * NN + jg) * NH;
#pragma unroll
            for (int q = 0; q < 4; q++) {
                float4 r0 = *(const float4*)&rel[rb + q * 8];
                float4 r1 = *(const float4*)&rel[rb + q * 8 + 4];
                float s[8];
                s[0] = ((const float*)&sS[0])[q] + r0.x;
                s[1] = ((const float*)&sS[1])[q] + r0.y;
                s[2] = ((const float*)&sS[2])[q] + r0.z;
                s[3] = ((const float*)&sS[3])[q] + r0.w;
                s[4] = ((const float*)&sS[4])[q] + r1.x;
                s[5] = ((const float*)&sS[5])[q] + r1.y;
                s[6] = ((const float*)&sS[6])[q] + r1.z;
                s[7] = ((const float*)&sS[7])[q] + r1.w;
                float m = s[0];
#pragma unroll
                for (int h = 1; h < 8; h++) m = fmaxf(m, s[h]);
                float sum = 0.f;
#pragma unroll
                for (int h = 0; h < 8; h++) { s[h] = __expf(s[h] - m); sum += s[h]; }
                const float inv = 1.f / sum;
#pragma unroll
                for (int h = 0; h < 8; h++) s[h] *= inv;
                *(float4*)&attn_g[rb + q * 8]     = make_float4(s[0], s[1], s[2], s[3]);
                *(float4*)&attn_g[rb + q * 8 + 4] = make_float4(s[4], s[5], s[6], s[7]);
                // tf32 split into A tiles, k = (jq+q)*8 + h
                float hi[8], lo[8];
#pragma unroll
                for (int h = 0; h < 8; h++) {
                    hi[h] = to_tf32(s[h]);
                    lo[h] = to_tf32(s[h] - hi[h]);
                }
                const int ko = il * AROW + (jq + q) * 8;
                *(float4*)&Ah[ko]     = make_float4(hi[0], hi[1], hi[2], hi[3]);
                *(float4*)&Ah[ko + 4] = make_float4(hi[4], hi[5], hi[6], hi[7]);
                *(float4*)&Al[ko]     = make_float4(lo[0], lo[1], lo[2], lo[3]);
                *(float4*)&Al[ko + 4] = make_float4(lo[4], lo[5], lo[6], lo[7]);
            }
        }
        __syncthreads();

        // ---- MMA phase: C[64x32] += A[64x64] * B[64x32], tf32x3 ----
        const int r0 = warp * 16 + gid;
#pragma unroll 2
        for (int ks = 0; ks < 8; ks++) {
            const int kb = ks * 8;
            u32 ah[4], al[4];
            ah[0] = __float_as_uint(Ah[r0 * AROW + kb + tig]);
            ah[1] = __float_as_uint(Ah[(r0 + 8) * AROW + kb + tig]);
            ah[2] = __float_as_uint(Ah[r0 * AROW + kb + tig + 4]);
            ah[3] = __float_as_uint(Ah[(r0 + 8) * AROW + kb + tig + 4]);
            al[0] = __float_as_uint(Al[r0 * AROW + kb + tig]);
            al[1] = __float_as_uint(Al[(r0 + 8) * AROW + kb + tig]);
            al[2] = __float_as_uint(Al[r0 * AROW + kb + tig + 4]);
            al[3] = __float_as_uint(Al[(r0 + 8) * AROW + kb + tig + 4]);
#pragma unroll
            for (int nt = 0; nt < 4; nt++) {
                const int n = nt * 8 + gid;
                u32 bh[2], bl[2];
                bh[0] = __float_as_uint(Bh[(kb + tig) * BROW + n]);
                bh[1] = __float_as_uint(Bh[(kb + tig + 4) * BROW + n]);
                bl[0] = __float_as_uint(Bl[(kb + tig) * BROW + n]);
                bl[1] = __float_as_uint(Bl[(kb + tig + 4) * BROW + n]);
                mma_tf32(acc[nt], ah, bh);
                mma_tf32(acc[nt], ah, bl);
                mma_tf32(acc[nt], al, bh);
            }
        }
    }

    // ---- epilogue: write K-split partials ----
    float* aop = g_AOp[blockIdx.x];
    const int row = i0 + warp * 16 + gid;
#pragma unroll
    for (int nt = 0; nt < 4; nt++) {
        const int dd = nt * 8 + 2 * tig;
        *(float2*)&aop[row * DD + dd]       = make_float2(acc[nt][0], acc[nt][1]);
        *(float2*)&aop[(row + 8) * DD + dd] = make_float2(acc[nt][2], acc[nt][3]);
    }
}

// ---------------------------------------------------------------------------
// Kernel 4: sum split partials, then out = relu(ao @ W1 + b1) @ W2 + b2.
// ---------------------------------------------------------------------------
__global__ __launch_bounds__(256) void mlp_kernel(
    const float* __restrict__ W1, const float* __restrict__ b1,
    const float* __restrict__ W2, const float* __restrict__ b2,
    float* __restrict__ out)
{
    __shared__ float aos[16][DD];
    __shared__ float hs[16][CH];

    const int tid = threadIdx.x;
    const int r0 = blockIdx.x * 16;

    for (int idx = tid; idx < 16 * DD; idx += 256) {
        const int off = (r0 + idx / DD) * DD + (idx % DD);
        float a = 0.f;
#pragma unroll
        for (int s = 0; s < KSPLIT; s++) a += g_AOp[s][off];
        aos[idx / DD][idx % DD] = a;
    }
    __syncthreads();

    const int c = tid;
    float w[DD];
#pragma unroll
    for (int k = 0; k < DD; k++) w[k] = W1[k * CH + c];
    const float bb1 = b1[c];
#pragma unroll 4
    for (int r = 0; r < 16; r++) {
        float a = bb1;
#pragma unroll
        for (int k = 0; k < DD; k++) a += aos[r][k] * w[k];
        hs[r][c] = fmaxf(a, 0.f);
    }
    __syncthreads();

    float acc2[16];
    const float bb2 = b2[c];
#pragma unroll
    for (int r = 0; r < 16; r++) acc2[r] = bb2;
#pragma unroll 4
    for (int k = 0; k < CH; k++) {
        const float wv = W2[k * CH + c];
#pragma unroll
        for (int r = 0; r < 16; r++) acc2[r] += hs[r][k] * wv;
    }
#pragma unroll
    for (int r = 0; r < 16; r++) out[(r0 + r) * CH + c] = acc2[r];
}

// ---------------------------------------------------------------------------
extern "C" void kernel_launch(void* const* d_in, const int* in_sizes, int n_in,
                              void* d_out, int out_size)
{
    const float* X   = (const float*)d_in[0];
    const float* rel = (const float*)d_in[1];
    // d_in[2] = num_nodes (unused; N fixed at 4096)
    const float* Wq = (const float*)d_in[3];
    const float* bq = (const float*)d_in[4];
    const float* Wk = (const float*)d_in[5];
    const float* bk = (const float*)d_in[6];
    const float* Wv = (const float*)d_in[7];
    const float* bv = (const float*)d_in[8];
    const float* W1 = (const float*)d_in[9];
    const float* b1 = (const float*)d_in[10];
    const float* W2 = (const float*)d_in[11];
    const float* b2 = (const float*)d_in[12];

    float* out    = (float*)d_out;           // [4096, 256]
    float* attn_g = out + (size_t)NN * CH;   // [4096, 4096, 8]

    cudaFuncSetAttribute(av_softmax,
                         cudaFuncAttributeMaxDynamicSharedMemorySize, AV_SMEM_BYTES);

    qkv_kernel<<<dim3(64, 4, 3), 256>>>(X, Wq, bq, Wk, bk, Wv, bv);
    score_gemm<<<dim3(NN / 64, NN / 64, NH), 128>>>();
    av_softmax<<<dim3(KSPLIT, NN / 64), 128, AV_SMEM_BYTES>>>(rel, attn_g);
    mlp_kernel<<<NN / 16, 256>>>(W1, b1, W2, b2, out);
}